// round 9
// baseline (speedup 1.0000x reference)
#include <cuda_runtime.h>
#include <cuda_fp16.h>

#define N_NODES 50000
#define DS 127
#define DPAD 128
#define NE 800000
#define EPSF 1e-7f
#define GR 64   // rows per gemm block

// g_h  : h1 = relu(agg1)+x (fp32), written by layer-2 gemm prologue; pad col = 0
// g_z  : gemm output in fp16 (row stride 128 halves); pad col = 0
// g_agg: fp16 atomic accumulation target; pad col garbage, never read
__device__ __align__(16) float  g_h[N_NODES * DPAD];
__device__ __align__(16) __half g_z[N_NODES * DPAD];
__device__ __align__(16) __half g_agg[N_NODES * DPAD];

// smem floats: WpA[8192] | WpB[8192] | h_s[64*128] | b_s[128] = 98816 B
// WpA[k2*128 + lane*4 + sub*2 + par] = W[2*k2+par][4*lane+sub],     sub in {0,1}
// WpB[k2*128 + lane*4 + sub*2 + par] = W[2*k2+par][4*lane+2+sub],   sub in {0,1}
// => one 16B lane entry = two f32x2 col-pairs {evenK,oddK}; 16B lane stride (conflict-free)
#define WB_OFF 8192
#define H_OFF  16384
#define B_OFF  (H_OFF + GR * DPAD)
#define SMEM_BYTES ((B_OFF + DPAD) * 4)

__device__ __forceinline__ float warp_sum(float v) {
#pragma unroll
    for (int o = 16; o; o >>= 1) v += __shfl_xor_sync(0xffffffffu, v, o);
    return v;
}

__device__ __forceinline__ void fma2(unsigned long long& acc,
                                     unsigned long long a, unsigned long long b) {
    asm("fma.rn.f32x2 %0, %1, %2, %0;" : "+l"(acc) : "l"(a), "l"(b));
}

extern __shared__ float smem[];

// z = half(h @ W + b); agg zeroed in epilogue.
// layer==0: h rows = x (logmap0(expmap0(x)) == x analytically).
// layer==1: h rows = relu(agg) + x (== h1), also stored to g_h for the final skip.
// 512 threads, 64 rows/block. Thread (cx=tid&31, ry=tid>>5): 4 rows x 4 cols.
// Accumulators f32x2 {even-k, odd-k} partial sums per column, halves added at end.
// 32-reg accumulator footprint -> no spills at 128-reg cap.
__global__ void __launch_bounds__(512, 1)
k_gemm(const float* __restrict__ W, const float* __restrict__ b,
       const float* __restrict__ x, int layer) {
    float* WpA = smem;
    float* WpB = smem + WB_OFF;
    float* h_s = smem + H_OFF;
    float* b_s = smem + B_OFF;
    int tid  = threadIdx.x;
    int row0 = blockIdx.x * GR;

    // W fill into split k-pair layout; zeros for k==127 or c==127
    for (int i = tid; i < DPAD * DPAD; i += 512) {
        int k = i >> 7, c = i & 127;
        float v = (k < DS && c < DS) ? W[k * DS + c] : 0.f;
        int k2 = k >> 1, par = k & 1, lane = c >> 2, sub = c & 3;
        float* dstp = (sub < 2) ? WpA : WpB;
        dstp[k2 * 128 + lane * 4 + (sub & 1) * 2 + par] = v;
    }
    if (tid < DPAD) b_s[tid] = (tid < DS) ? b[tid] : 0.f;

    // h tile; pad col 127 -> 0
    {
        int c = tid & 127, rr = tid >> 7;   // rr in 0..3
        const __half* aggh = g_agg;
        for (int r = rr; r < GR; r += 4) {
            int row = row0 + r;
            float v = 0.f;
            if (row < N_NODES) {
                if (c < DS) {
                    v = x[row * DS + c];
                    if (layer) {
                        v += fmaxf(__half2float(aggh[row * DPAD + c]), 0.f);
                        g_h[row * DPAD + c] = v;
                    }
                } else if (layer) {
                    g_h[row * DPAD + c] = 0.f;   // pad col of h1
                }
            }
            h_s[r * DPAD + c] = v;
        }
    }
    __syncthreads();

    int cx = tid & 31;
    int ry = tid >> 5;   // 0..15

    unsigned long long acc[4][4];
#pragma unroll
    for (int r = 0; r < 4; r++)
#pragma unroll
        for (int j = 0; j < 4; j++) acc[r][j] = 0ull;

    const ulonglong2* WA  = (const ulonglong2*)WpA;   // [k2*32 + cx]
    const ulonglong2* WB  = (const ulonglong2*)WpB;   // [k2*32 + cx]
    const ulonglong2* H16 = (const ulonglong2*)h_s;   // [row*32 + kk] = {h4kk..h4kk+3}

#pragma unroll 2
    for (int kk = 0; kk < 32; kk++) {   // kk = k2/2; covers k = 4kk .. 4kk+3
        ulonglong2 wA0 = WA[(2 * kk)     * 32 + cx];
        ulonglong2 wB0 = WB[(2 * kk)     * 32 + cx];
        ulonglong2 wA1 = WA[(2 * kk + 1) * 32 + cx];
        ulonglong2 wB1 = WB[(2 * kk + 1) * 32 + cx];
#pragma unroll
        for (int r = 0; r < 4; r++) {
            ulonglong2 h = H16[(ry * 4 + r) * 32 + kk];  // broadcast, 16B
            fma2(acc[r][0], h.x, wA0.x);
            fma2(acc[r][1], h.x, wA0.y);
            fma2(acc[r][2], h.x, wB0.x);
            fma2(acc[r][3], h.x, wB0.y);
            fma2(acc[r][0], h.y, wA1.x);
            fma2(acc[r][1], h.y, wA1.y);
            fma2(acc[r][2], h.y, wB1.x);
            fma2(acc[r][3], h.y, wB1.y);
        }
    }

    float4 bb = ((const float4*)b_s)[cx];
    uint2* z2 = (uint2*)g_z;     // 8B = 4 halves; 32 per row
    uint2* a2 = (uint2*)g_agg;
#pragma unroll
    for (int r = 0; r < 4; r++) {
        int row = row0 + ry * 4 + r;
        if (row < N_NODES) {
            float2 p0 = *(float2*)&acc[r][0];
            float2 p1 = *(float2*)&acc[r][1];
            float2 p2 = *(float2*)&acc[r][2];
            float2 p3 = *(float2*)&acc[r][3];
            __half2 h0 = __floats2half2_rn(p0.x + p0.y + bb.x, p1.x + p1.y + bb.y);
            __half2 h1 = __floats2half2_rn(p2.x + p2.y + bb.z, p3.x + p3.y + bb.w);
            uint2 o;
            o.x = *(unsigned*)&h0;
            o.y = *(unsigned*)&h1;
            z2[row * 32 + cx] = o;
            a2[row * 32 + cx] = make_uint2(0u, 0u);
        }
    }
}

// Warp processes 8 edges: lanes 0-7 load metadata, shuffle-broadcast, then
// 8 overlapped 256B fp16 row loads (MLP=8) followed by 8 fp16x2 v2 reductions.
// NE % 8 == 0, grid sized exactly -> no bounds checks.
__global__ void k_edge(const int* __restrict__ src, const int* __restrict__ dst,
                       const float* __restrict__ wt) {
    int warp = (blockIdx.x * blockDim.x + threadIdx.x) >> 5;
    int lane = threadIdx.x & 31;
    int e0 = warp * 8;

    int s = 0, d = 0;
    float w = 0.f;
    if (lane < 8) {
        s = src[e0 + lane];
        d = dst[e0 + lane];
        w = wt[e0 + lane];
    }

    const uint2* z2 = (const uint2*)g_z;   // 4 halves per lane -> cols 4lane..4lane+3
    uint2 v[8];
#pragma unroll
    for (int i = 0; i < 8; i++) {
        int si = __shfl_sync(0xffffffffu, s, i);
        v[i] = z2[si * 32 + lane];
    }
#pragma unroll
    for (int i = 0; i < 8; i++) {
        int   di = __shfl_sync(0xffffffffu, d, i);
        float wi = __shfl_sync(0xffffffffu, w, i);
        float2 f0 = __half22float2(*(const __half2*)&v[i].x);
        float2 f1 = __half22float2(*(const __half2*)&v[i].y);
        __half2 m0 = __floats2half2_rn(f0.x * wi, f0.y * wi);
        __half2 m1 = __floats2half2_rn(f1.x * wi, f1.y * wi);
        __half* a = g_agg + di * DPAD + 4 * lane;
        asm volatile("red.global.add.noftz.v2.f16x2 [%0], {%1,%2};"
                     :: "l"(a), "r"(*(unsigned*)&m0), "r"(*(unsigned*)&m1)
                     : "memory");
    }
}

// h2 = relu(agg2) + h1;  out = expmap0(h2): out[i,0]=cosh(n), out[i,1+c]=sinh(n)*h_c/n
__global__ void k_final(float* __restrict__ out) {
    int warp = (blockIdx.x * blockDim.x + threadIdx.x) >> 5;
    int lane = threadIdx.x & 31;
    if (warp >= N_NODES) return;
    float v[4];
    float n2 = 0.f;
#pragma unroll
    for (int j = 0; j < 4; j++) {
        int c = lane + 32 * j;
        float a  = __half2float(g_agg[warp * DPAD + c]);
        float hv = g_h[warp * DPAD + c];
        v[j] = (c < DS) ? (fmaxf(a, 0.f) + hv) : 0.f;
        n2 += v[j] * v[j];
    }
    n2 = warp_sum(n2);
    float n = fmaxf(sqrtf(n2), EPSF);
    float t = coshf(n);
    float f = sinhf(n) / n;
    if (lane == 0) out[warp * DPAD] = t;
#pragma unroll
    for (int j = 0; j < 4; j++) {
        int c = lane + 32 * j;
        if (c < DS) out[warp * DPAD + 1 + c] = f * v[j];
    }
}

extern "C" void kernel_launch(void* const* d_in, const int* in_sizes, int n_in,
                              void* d_out, int out_size) {
    const float* x  = (const float*)d_in[0];
    const float* W1 = (const float*)d_in[1];
    const float* b1 = (const float*)d_in[2];
    const float* W2 = (const float*)d_in[3];
    const float* b2 = (const float*)d_in[4];
    const int*   es = (const int*)d_in[5];
    const int*   ed = (const int*)d_in[6];
    const float* ew = (const float*)d_in[7];
    float* out = (float*)d_out;

    cudaFuncSetAttribute(k_gemm, cudaFuncAttributeMaxDynamicSharedMemorySize, SMEM_BYTES);

    int gemm_blocks = (N_NODES + GR - 1) / GR;       // 782
    int edge_blocks = (NE / 8) / 8;                  // 12500 (8 warps/block, 8 edges/warp)
    int row_blocks  = (N_NODES * 32 + 255) / 256;    // 6250

    k_gemm<<<gemm_blocks, 512, SMEM_BYTES>>>(W1, b1, x, 0);
    k_edge<<<edge_blocks, 256>>>(es, ed, ew);

    k_gemm<<<gemm_blocks, 512, SMEM_BYTES>>>(W2, b2, x, 1);
    k_edge<<<edge_blocks, 256>>>(es, ed, ew);

    k_final<<<row_blocks, 256>>>(out);
}

// round 10
// speedup vs baseline: 1.6405x; 1.6405x over previous
#include <cuda_runtime.h>
#include <cuda_fp16.h>
#include <cstdint>

#define N_NODES 50000
#define DS 127
#define DPAD 128
#define NE 800000
#define EPSF 1e-7f
#define GR 128      // rows per gemm block
#define HSTRIDE 136 // smem stride in halves (conflict-free ldmatrix)

// g_h  : h1 = relu(agg1)+x (fp32), written by layer-2 gemm prologue; pad col = 0
// g_z  : gemm output fp16 (row stride 128); pad col = 0
// g_agg: fp16 atomic accumulation target; pad col garbage, never read
// g_Wt : W1,W2 as fp16, n-major [n][k] 128x128 each, pads zero
__device__ __align__(16) float  g_h[N_NODES * DPAD];
__device__ __align__(16) __half g_z[N_NODES * DPAD];
__device__ __align__(16) __half g_agg[N_NODES * DPAD];
__device__ __align__(16) __half g_Wt[2 * DPAD * DPAD];

__device__ __forceinline__ float warp_sum(float v) {
#pragma unroll
    for (int o = 16; o; o >>= 1) v += __shfl_xor_sync(0xffffffffu, v, o);
    return v;
}

__device__ __forceinline__ void ldsm4(uint32_t* r, uint32_t addr) {
    asm volatile("ldmatrix.sync.aligned.m8n8.x4.shared.b16 {%0,%1,%2,%3}, [%4];"
                 : "=r"(r[0]), "=r"(r[1]), "=r"(r[2]), "=r"(r[3]) : "r"(addr));
}

__device__ __forceinline__ void mma16816(float* c, const uint32_t* a,
                                         uint32_t b0, uint32_t b1) {
    asm volatile(
        "mma.sync.aligned.m16n8k16.row.col.f32.f16.f16.f32 "
        "{%0,%1,%2,%3}, {%4,%5,%6,%7}, {%8,%9}, {%0,%1,%2,%3};"
        : "+f"(c[0]), "+f"(c[1]), "+f"(c[2]), "+f"(c[3])
        : "r"(a[0]), "r"(a[1]), "r"(a[2]), "r"(a[3]), "r"(b0), "r"(b1));
}

// g_Wt[l][n*128+k] = fp16(W_l[k*127+n]); zero pads (k==127 or n==127)
__global__ void k_prep(const float* __restrict__ W1, const float* __restrict__ W2) {
    int idx = blockIdx.x * 256 + threadIdx.x;
    if (idx >= 2 * DPAD * DPAD) return;
    int l = idx >> 14, rem = idx & 16383, n = rem >> 7, k = rem & 127;
    const float* W = l ? W2 : W1;
    float v = (k < DS && n < DS) ? W[k * DS + n] : 0.f;
    g_Wt[idx] = __float2half(v);
}

// z = half(h @ W + b) via HMMA; agg zeroed in epilogue.
// layer==0: h = x (logmap0(expmap0(x)) == x analytically).
// layer==1: h = relu(agg) + x (== h1), also stored fp32 to g_h for the final skip.
// 256 threads = 8 warps: warp (wm=wid>>1, wn=wid&1) computes rows [wm*32,+32) x cols [wn*64,+64).
__global__ void __launch_bounds__(256, 2)
k_gemm(const float* __restrict__ b, const float* __restrict__ x, int layer) {
    extern __shared__ __align__(16) char smem_raw[];
    __half* Wt  = (__half*)smem_raw;                 // [128][136]
    __half* Ht  = Wt + DPAD * HSTRIDE;               // [128][136]
    float*  b_s = (float*)(Ht + DPAD * HSTRIDE);     // [128]
    int tid  = threadIdx.x;
    int row0 = blockIdx.x * GR;

    // Wt smem fill: 2048 x 16B chunks from dense n-major g_Wt into stride-136 layout
    {
        const uint4* src = (const uint4*)(g_Wt + layer * DPAD * DPAD);
        for (int j = tid; j < 2048; j += 256) {
            int n = j >> 4, kc = j & 15;
            *(uint4*)(Wt + n * HSTRIDE + kc * 8) = src[j];
        }
    }
    if (tid < DPAD) b_s[tid] = (tid < DS) ? b[tid] : 0.f;

    // h tile fp16 (pads -> 0); layer 1 also writes fp32 h1 to g_h
    {
        int c2 = (tid & 63) * 2, rr = tid >> 6;   // rr in 0..3
        for (int r = rr; r < GR; r += 4) {
            int row = row0 + r;
            float v0 = 0.f, v1 = 0.f;
            if (row < N_NODES) {
                v0 = x[row * DS + c2];
                if (c2 < 126) v1 = x[row * DS + c2 + 1];
                if (layer) {
                    v0 += fmaxf(__half2float(g_agg[row * DPAD + c2]), 0.f);
                    if (c2 < 126) v1 += fmaxf(__half2float(g_agg[row * DPAD + c2 + 1]), 0.f);
                    g_h[row * DPAD + c2]     = v0;
                    g_h[row * DPAD + c2 + 1] = v1;
                }
            }
            *(__half2*)(Ht + r * HSTRIDE + c2) = __floats2half2_rn(v0, v1);
        }
    }
    __syncthreads();

    int lane = tid & 31, wid = tid >> 5;
    int wm = wid >> 1, wn = wid & 1;

    // ldmatrix lane addresses (byte offsets into shared space)
    uint32_t ht_s = (uint32_t)__cvta_generic_to_shared(Ht);
    uint32_t wt_s = (uint32_t)__cvta_generic_to_shared(Wt);
    // A: lanes 0-7 rows0-7/k0, 8-15 rows8-15/k0, 16-23 rows0-7/k8, 24-31 rows8-15/k8
    uint32_t aaddr[2];
#pragma unroll
    for (int mt = 0; mt < 2; mt++) {
        int rowA = wm * 32 + mt * 16 + (lane & 15);
        int kA   = (lane >> 4) * 8;
        aaddr[mt] = ht_s + (uint32_t)(rowA * HSTRIDE + kA) * 2;
    }
    // B: r0 = nt_even/k0, r1 = nt_even/k8, r2 = nt_odd/k0, r3 = nt_odd/k8
    uint32_t baddr[4];
#pragma unroll
    for (int p = 0; p < 4; p++) {
        int rowB = wn * 64 + p * 16 + (lane >> 4) * 8 + (lane & 7);
        int kB   = ((lane >> 3) & 1) * 8;
        baddr[p] = wt_s + (uint32_t)(rowB * HSTRIDE + kB) * 2;
    }

    float c[2][8][4];
#pragma unroll
    for (int mt = 0; mt < 2; mt++)
#pragma unroll
        for (int nt = 0; nt < 8; nt++)
#pragma unroll
            for (int j = 0; j < 4; j++) c[mt][nt][j] = 0.f;

#pragma unroll
    for (int ks = 0; ks < 8; ks++) {
        uint32_t kb = (uint32_t)(ks * 16 * 2);
        uint32_t a[2][4], bq[4][4];
        ldsm4(a[0], aaddr[0] + kb);
        ldsm4(a[1], aaddr[1] + kb);
#pragma unroll
        for (int p = 0; p < 4; p++) ldsm4(bq[p], baddr[p] + kb);
#pragma unroll
        for (int mt = 0; mt < 2; mt++)
#pragma unroll
            for (int nt = 0; nt < 8; nt++)
                mma16816(c[mt][nt], a[mt], bq[nt >> 1][(nt & 1) * 2],
                         bq[nt >> 1][(nt & 1) * 2 + 1]);
    }

    // epilogue: z = half(acc + bias); zero agg
    int r_in = lane >> 2, col_in = 2 * (lane & 3);
#pragma unroll
    for (int mt = 0; mt < 2; mt++) {
#pragma unroll
        for (int nt = 0; nt < 8; nt++) {
            int row = row0 + wm * 32 + mt * 16 + r_in;
            int col = wn * 64 + nt * 8 + col_in;
            float bb0 = b_s[col], bb1 = b_s[col + 1];
            if (row < N_NODES)
                *(__half2*)(g_z + row * DPAD + col) =
                    __floats2half2_rn(c[mt][nt][0] + bb0, c[mt][nt][1] + bb1);
            if (row + 8 < N_NODES)
                *(__half2*)(g_z + (row + 8) * DPAD + col) =
                    __floats2half2_rn(c[mt][nt][2] + bb0, c[mt][nt][3] + bb1);
        }
    }
    {
        uint4 zz = make_uint4(0u, 0u, 0u, 0u);
        uint4* a4 = (uint4*)(g_agg + (size_t)row0 * DPAD);
        for (int j = tid; j < 2048; j += 256) {
            int row = row0 + (j >> 4);
            if (row < N_NODES) a4[j] = zz;
        }
    }
}

// Warp processes 8 edges: lanes 0-7 load metadata, shuffle-broadcast, then
// 8 overlapped 256B fp16 row loads (MLP=8) followed by 8 fp16x2 v2 reductions.
__global__ void k_edge(const int* __restrict__ src, const int* __restrict__ dst,
                       const float* __restrict__ wt) {
    int warp = (blockIdx.x * blockDim.x + threadIdx.x) >> 5;
    int lane = threadIdx.x & 31;
    int e0 = warp * 8;

    int s = 0, d = 0;
    float w = 0.f;
    if (lane < 8) {
        s = src[e0 + lane];
        d = dst[e0 + lane];
        w = wt[e0 + lane];
    }

    const uint2* z2 = (const uint2*)g_z;   // 4 halves per lane
    uint2 v[8];
#pragma unroll
    for (int i = 0; i < 8; i++) {
        int si = __shfl_sync(0xffffffffu, s, i);
        v[i] = z2[si * 32 + lane];
    }
#pragma unroll
    for (int i = 0; i < 8; i++) {
        int   di = __shfl_sync(0xffffffffu, d, i);
        float wi = __shfl_sync(0xffffffffu, w, i);
        float2 f0 = __half22float2(*(const __half2*)&v[i].x);
        float2 f1 = __half22float2(*(const __half2*)&v[i].y);
        __half2 m0 = __floats2half2_rn(f0.x * wi, f0.y * wi);
        __half2 m1 = __floats2half2_rn(f1.x * wi, f1.y * wi);
        __half* a = g_agg + di * DPAD + 4 * lane;
        asm volatile("red.global.add.noftz.v2.f16x2 [%0], {%1,%2};"
                     :: "l"(a), "r"(*(unsigned*)&m0), "r"(*(unsigned*)&m1)
                     : "memory");
    }
}

// h2 = relu(agg2) + h1;  out = expmap0(h2)
__global__ void k_final(float* __restrict__ out) {
    int warp = (blockIdx.x * blockDim.x + threadIdx.x) >> 5;
    int lane = threadIdx.x & 31;
    if (warp >= N_NODES) return;
    float v[4];
    float n2 = 0.f;
#pragma unroll
    for (int j = 0; j < 4; j++) {
        int c = lane + 32 * j;
        float a  = __half2float(g_agg[warp * DPAD + c]);
        float hv = g_h[warp * DPAD + c];
        v[j] = (c < DS) ? (fmaxf(a, 0.f) + hv) : 0.f;
        n2 += v[j] * v[j];
    }
    n2 = warp_sum(n2);
    float n = fmaxf(sqrtf(n2), EPSF);
    float t = coshf(n);
    float f = sinhf(n) / n;
    if (lane == 0) out[warp * DPAD] = t;
#pragma unroll
    for (int j = 0; j < 4; j++) {
        int c = lane + 32 * j;
        if (c < DS) out[warp * DPAD + 1 + c] = f * v[j];
    }
}

extern "C" void kernel_launch(void* const* d_in, const int* in_sizes, int n_in,
                              void* d_out, int out_size) {
    const float* x  = (const float*)d_in[0];
    const float* W1 = (const float*)d_in[1];
    const float* b1 = (const float*)d_in[2];
    const float* W2 = (const float*)d_in[3];
    const float* b2 = (const float*)d_in[4];
    const int*   es = (const int*)d_in[5];
    const int*   ed = (const int*)d_in[6];
    const float* ew = (const float*)d_in[7];
    float* out = (float*)d_out;

    const int smem_bytes = (2 * DPAD * HSTRIDE) * 2 + DPAD * 4;   // 70144
    cudaFuncSetAttribute(k_gemm, cudaFuncAttributeMaxDynamicSharedMemorySize, smem_bytes);

    int gemm_blocks = (N_NODES + GR - 1) / GR;       // 391
    int edge_blocks = (NE / 8) / 8;                  // 12500
    int row_blocks  = (N_NODES * 32 + 255) / 256;    // 6250

    k_prep<<<(2 * DPAD * DPAD + 255) / 256, 256>>>(W1, W2);

    k_gemm<<<gemm_blocks, 256, smem_bytes>>>(b1, x, 0);
    k_edge<<<edge_blocks, 256>>>(es, ed, ew);

    k_gemm<<<gemm_blocks, 256, smem_bytes>>>(b2, x, 1);
    k_edge<<<edge_blocks, 256>>>(es, ed, ew);

    k_final<<<row_blocks, 256>>>(out);
}

// round 11
// speedup vs baseline: 2.0564x; 1.2535x over previous
#include <cuda_runtime.h>
#include <cuda_fp16.h>
#include <cstdint>

#define N_NODES 50000
#define DS 127
#define DPAD 128
#define NE 800000
#define EPSF 1e-7f
#define GR 64       // rows per gemm block
#define HSTRIDE 136 // smem stride in halves (conflict-free ldmatrix)

// g_x16: x as fp16, padded [N][128], pad col 0
// g_h16: h1 = relu(agg1)+x as fp16 (layer-2 prologue), pad col 0
// g_z  : gemm output fp16; pad col 0
// g_agg: fp16 atomic accumulation target; pad col garbage, never read
// g_Wt : W1,W2 as fp16, n-major [n][k] 128x128 each, pads zero
__device__ __align__(16) __half g_x16[N_NODES * DPAD];
__device__ __align__(16) __half g_h16[N_NODES * DPAD];
__device__ __align__(16) __half g_z[N_NODES * DPAD];
__device__ __align__(16) __half g_agg[N_NODES * DPAD];
__device__ __align__(16) __half g_Wt[2 * DPAD * DPAD];

__device__ __forceinline__ float warp_sum(float v) {
#pragma unroll
    for (int o = 16; o; o >>= 1) v += __shfl_xor_sync(0xffffffffu, v, o);
    return v;
}

__device__ __forceinline__ void ldsm4(uint32_t* r, uint32_t addr) {
    asm volatile("ldmatrix.sync.aligned.m8n8.x4.shared.b16 {%0,%1,%2,%3}, [%4];"
                 : "=r"(r[0]), "=r"(r[1]), "=r"(r[2]), "=r"(r[3]) : "r"(addr));
}

__device__ __forceinline__ void mma16816(float* c, const uint32_t* a,
                                         uint32_t b0, uint32_t b1) {
    asm volatile(
        "mma.sync.aligned.m16n8k16.row.col.f32.f16.f16.f32 "
        "{%0,%1,%2,%3}, {%4,%5,%6,%7}, {%8,%9}, {%0,%1,%2,%3};"
        : "+f"(c[0]), "+f"(c[1]), "+f"(c[2]), "+f"(c[3])
        : "r"(a[0]), "r"(a[1]), "r"(a[2]), "r"(a[3]), "r"(b0), "r"(b1));
}

// g_Wt[l][n*128+k] = fp16(W_l[k*127+n]); zero pads
__global__ void k_prepW(const float* __restrict__ W1, const float* __restrict__ W2) {
    int idx = blockIdx.x * 256 + threadIdx.x;
    if (idx >= 2 * DPAD * DPAD) return;
    int l = idx >> 14, rem = idx & 16383, n = rem >> 7, k = rem & 127;
    const float* W = l ? W2 : W1;
    float v = (k < DS && n < DS) ? W[k * DS + n] : 0.f;
    g_Wt[idx] = __float2half(v);
}

// g_x16[row*128+c] = fp16(x[row*127+c]); pad col 0
__global__ void k_prepX(const float* __restrict__ x) {
    int idx = blockIdx.x * 256 + threadIdx.x;
    if (idx >= N_NODES * DPAD) return;
    int row = idx >> 7, c = idx & 127;
    g_x16[idx] = __float2half((c < DS) ? x[row * DS + c] : 0.f);
}

// z = half(h @ W + b) via HMMA; agg zeroed in epilogue.
// layer==0: h = x16.  layer==1: h = relu(agg) + x16 (== h1), stored fp16 to g_h16.
// 256 threads = 8 warps: warp (wm=wid>>2, wn=wid&3) = rows [wm*32,+32) x cols [wn*32,+32).
__global__ void __launch_bounds__(256, 3)
k_gemm(const float* __restrict__ b, int layer) {
    extern __shared__ __align__(16) char smem_raw[];
    __half* Wt  = (__half*)smem_raw;                 // [128][136]
    __half* Ht  = Wt + DPAD * HSTRIDE;               // [64][136]
    float*  b_s = (float*)(Ht + GR * HSTRIDE);       // [128]
    int tid  = threadIdx.x;
    int row0 = blockIdx.x * GR;

    // Wt smem fill: 2048 x 16B chunks
    {
        const uint4* src = (const uint4*)(g_Wt + layer * DPAD * DPAD);
        for (int j = tid; j < 2048; j += 256) {
            int n = j >> 4, kc = j & 15;
            *(uint4*)(Wt + n * HSTRIDE + kc * 8) = src[j];
        }
    }
    if (tid < DPAD) b_s[tid] = (tid < DS) ? b[tid] : 0.f;

    // h tile fp16: 64 rows x 16 uint4 chunks (8 halves each)
    for (int j = tid; j < GR * 16; j += 256) {
        int r = j >> 4, ch = j & 15;
        int row = row0 + r;
        uint4 v = make_uint4(0u, 0u, 0u, 0u);
        if (row < N_NODES) {
            v = ((const uint4*)(g_x16 + (size_t)row * DPAD))[ch];
            if (layer) {
                uint4 a = ((const uint4*)(g_agg + (size_t)row * DPAD))[ch];
                __half2* vh = (__half2*)&v;
                __half2* ah = (__half2*)&a;
#pragma unroll
                for (int i = 0; i < 4; i++) {
                    float2 xf = __half22float2(vh[i]);
                    float2 af = __half22float2(ah[i]);
                    vh[i] = __floats2half2_rn(xf.x + fmaxf(af.x, 0.f),
                                              xf.y + fmaxf(af.y, 0.f));
                }
                ((uint4*)(g_h16 + (size_t)row * DPAD))[ch] = v;
            }
        }
        *(uint4*)(Ht + r * HSTRIDE + ch * 8) = v;
    }
    __syncthreads();

    int lane = tid & 31, wid = tid >> 5;
    int wm = wid >> 2, wn = wid & 3;

    uint32_t ht_s = (uint32_t)__cvta_generic_to_shared(Ht);
    uint32_t wt_s = (uint32_t)__cvta_generic_to_shared(Wt);
    // A tiles: 16 rows x 16 k per ldsm4
    uint32_t aaddr[2];
#pragma unroll
    for (int mt = 0; mt < 2; mt++) {
        int rowA = wm * 32 + mt * 16 + (lane & 15);
        int kA   = (lane >> 4) * 8;
        aaddr[mt] = ht_s + (uint32_t)(rowA * HSTRIDE + kA) * 2;
    }
    // B tiles: 16 n-rows x 16 k per ldsm4; p = 0,1 covers 32 cols
    uint32_t baddr[2];
#pragma unroll
    for (int p = 0; p < 2; p++) {
        int rowB = wn * 32 + p * 16 + (lane >> 4) * 8 + (lane & 7);
        int kB   = ((lane >> 3) & 1) * 8;
        baddr[p] = wt_s + (uint32_t)(rowB * HSTRIDE + kB) * 2;
    }

    float c[2][4][4];
#pragma unroll
    for (int mt = 0; mt < 2; mt++)
#pragma unroll
        for (int nt = 0; nt < 4; nt++)
#pragma unroll
            for (int j = 0; j < 4; j++) c[mt][nt][j] = 0.f;

#pragma unroll
    for (int ks = 0; ks < 8; ks++) {
        uint32_t kb = (uint32_t)(ks * 16 * 2);
        uint32_t a[2][4], bq[2][4];
        ldsm4(a[0], aaddr[0] + kb);
        ldsm4(a[1], aaddr[1] + kb);
        ldsm4(bq[0], baddr[0] + kb);
        ldsm4(bq[1], baddr[1] + kb);
#pragma unroll
        for (int mt = 0; mt < 2; mt++)
#pragma unroll
            for (int nt = 0; nt < 4; nt++)
                mma16816(c[mt][nt], a[mt], bq[nt >> 1][(nt & 1) * 2],
                         bq[nt >> 1][(nt & 1) * 2 + 1]);
    }

    // epilogue: z = half(acc + bias); zero agg
    int r_in = lane >> 2, col_in = 2 * (lane & 3);
#pragma unroll
    for (int mt = 0; mt < 2; mt++) {
#pragma unroll
        for (int nt = 0; nt < 4; nt++) {
            int row = row0 + wm * 32 + mt * 16 + r_in;
            int col = wn * 32 + nt * 8 + col_in;
            float bb0 = b_s[col], bb1 = b_s[col + 1];
            if (row < N_NODES)
                *(__half2*)(g_z + (size_t)row * DPAD + col) =
                    __floats2half2_rn(c[mt][nt][0] + bb0, c[mt][nt][1] + bb1);
            if (row + 8 < N_NODES)
                *(__half2*)(g_z + (size_t)(row + 8) * DPAD + col) =
                    __floats2half2_rn(c[mt][nt][2] + bb0, c[mt][nt][3] + bb1);
        }
    }
    {
        uint4 zz = make_uint4(0u, 0u, 0u, 0u);
        uint4* a4 = (uint4*)(g_agg + (size_t)row0 * DPAD);
        for (int j = tid; j < GR * 16; j += 256) {
            int row = row0 + (j >> 4);
            if (row < N_NODES) a4[j] = zz;
        }
    }
}

// Warp processes 8 edges: lanes 0-7 load metadata, shuffle-broadcast, then
// 8 overlapped 256B fp16 row loads (MLP=8) followed by 8 fp16x2 v2 reductions.
__global__ void k_edge(const int* __restrict__ src, const int* __restrict__ dst,
                       const float* __restrict__ wt) {
    int warp = (blockIdx.x * blockDim.x + threadIdx.x) >> 5;
    int lane = threadIdx.x & 31;
    int e0 = warp * 8;

    int s = 0, d = 0;
    float w = 0.f;
    if (lane < 8) {
        s = src[e0 + lane];
        d = dst[e0 + lane];
        w = wt[e0 + lane];
    }

    const uint2* z2 = (const uint2*)g_z;
    uint2 v[8];
#pragma unroll
    for (int i = 0; i < 8; i++) {
        int si = __shfl_sync(0xffffffffu, s, i);
        v[i] = z2[si * 32 + lane];
    }
#pragma unroll
    for (int i = 0; i < 8; i++) {
        int   di = __shfl_sync(0xffffffffu, d, i);
        float wi = __shfl_sync(0xffffffffu, w, i);
        float2 f0 = __half22float2(*(const __half2*)&v[i].x);
        float2 f1 = __half22float2(*(const __half2*)&v[i].y);
        __half2 m0 = __floats2half2_rn(f0.x * wi, f0.y * wi);
        __half2 m1 = __floats2half2_rn(f1.x * wi, f1.y * wi);
        __half* a = g_agg + di * DPAD + 4 * lane;
        asm volatile("red.global.add.noftz.v2.f16x2 [%0], {%1,%2};"
                     :: "l"(a), "r"(*(unsigned*)&m0), "r"(*(unsigned*)&m1)
                     : "memory");
    }
}

// h2 = relu(agg2) + h1;  out = expmap0(h2)
__global__ void k_final(float* __restrict__ out) {
    int warp = (blockIdx.x * blockDim.x + threadIdx.x) >> 5;
    int lane = threadIdx.x & 31;
    if (warp >= N_NODES) return;
    float v[4];
    float n2 = 0.f;
#pragma unroll
    for (int j = 0; j < 4; j++) {
        int c = lane + 32 * j;
        float a  = __half2float(g_agg[warp * DPAD + c]);
        float hv = __half2float(g_h16[warp * DPAD + c]);
        v[j] = (c < DS) ? (fmaxf(a, 0.f) + hv) : 0.f;
        n2 += v[j] * v[j];
    }
    n2 = warp_sum(n2);
    float n = fmaxf(sqrtf(n2), EPSF);
    float t = coshf(n);
    float f = sinhf(n) / n;
    if (lane == 0) out[warp * DPAD] = t;
#pragma unroll
    for (int j = 0; j < 4; j++) {
        int c = lane + 32 * j;
        if (c < DS) out[warp * DPAD + 1 + c] = f * v[j];
    }
}

extern "C" void kernel_launch(void* const* d_in, const int* in_sizes, int n_in,
                              void* d_out, int out_size) {
    const float* x  = (const float*)d_in[0];
    const float* W1 = (const float*)d_in[1];
    const float* b1 = (const float*)d_in[2];
    const float* W2 = (const float*)d_in[3];
    const float* b2 = (const float*)d_in[4];
    const int*   es = (const int*)d_in[5];
    const int*   ed = (const int*)d_in[6];
    const float* ew = (const float*)d_in[7];
    float* out = (float*)d_out;

    const int smem_bytes = (DPAD * HSTRIDE + GR * HSTRIDE) * 2 + DPAD * 4;  // 52736
    cudaFuncSetAttribute(k_gemm, cudaFuncAttributeMaxDynamicSharedMemorySize, smem_bytes);

    int gemm_blocks = (N_NODES + GR - 1) / GR;       // 782
    int edge_blocks = (NE / 8) / 8;                  // 12500
    int row_blocks  = (N_NODES * 32 + 255) / 256;    // 6250

    k_prepW<<<(2 * DPAD * DPAD + 255) / 256, 256>>>(W1, W2);
    k_prepX<<<(N_NODES * DPAD + 255) / 256, 256>>>(x);

    k_gemm<<<gemm_blocks, 256, smem_bytes>>>(b1, 0);
    k_edge<<<edge_blocks, 256>>>(es, ed, ew);

    k_gemm<<<gemm_blocks, 256, smem_bytes>>>(b2, 1);
    k_edge<<<edge_blocks, 256>>>(es, ed, ew);

    k_final<<<row_blocks, 256>>>(out);
}